// round 9
// baseline (speedup 1.0000x reference)
#include <cuda_runtime.h>
#include <cuda_bf16.h>
#include <cstdint>

// N = 400 nodes, E = N*(N-1) = 159600 edges, B = 32 batch.
// Output [B, E, 2] f32: out[b,e,:] = adj[i,j]!=0 ? (0,1) : (1,0),
// edge e -> (i = e/399, j = r + (r>=i)), r = e%399  (np.where(~eye) order).
//
// Batch-invariant output; every prior variant pinned at ~4.3 TB/s of stores.
// This round tests the wavefront/instruction-rate hypothesis:
//   - 256-bit stores (st.global.v8.f32, STG.256 on sm_10x): one store per
//     32 B instead of two STG.128s.
//   - per-CTA chunks in whole 128 B units so every warp store is
//     line-aligned (no 5-line straddled 512 B warp stores).
// Each thread computes 4 edges (8 floats) once, broadcasts to 32 batches.

#define N_NODES 400
#define N_M1    399
#define E_PAIRS 79800            // float4 (2-edge) elements per batch
#define E_V8    39900            // v8 (4-edge, 32B) elements per batch
#define N_UNITS 9975             // 128B units per batch (E_V8 / 4)
#define BATCH   32
#define GRID_X  148
#define THREADS 256
#define UNIT_LO 67               // 148*67 = 9916; first 59 CTAs take 68
#define UREM    59               // 59*68 + 89*67 = 9975

// Compute one-hot pair for edge-pair p (edges 2p, 2p+1) -> 4 floats.
__device__ __forceinline__ float4 pair_val(const float* __restrict__ adj, int p)
{
    const int e0 = 2 * p;
    const int e1 = e0 + 1;
    int i0 = e0 / N_M1;
    int r0 = e0 - i0 * N_M1;
    int j0 = r0 + (r0 >= i0 ? 1 : 0);
    int i1 = e1 / N_M1;
    int r1 = e1 - i1 * N_M1;
    int j1 = r1 + (r1 >= i1 ? 1 : 0);
    const float t0 = (__ldg(&adj[i0 * N_NODES + j0]) != 0.0f) ? 1.0f : 0.0f;
    const float t1 = (__ldg(&adj[i1 * N_NODES + j1]) != 0.0f) ? 1.0f : 0.0f;
    return make_float4(1.0f - t0, t0, 1.0f - t1, t1);
}

__device__ __forceinline__ void do_v8(const float* __restrict__ adj,
                                      float* __restrict__ outf, int q)
{
    // v8 element q covers edge-pairs 2q and 2q+1 (edges 4q..4q+3).
    const float4 a = pair_val(adj, 2 * q);
    const float4 b = pair_val(adj, 2 * q + 1);

    float* dst = outf + (size_t)q * 8;
#pragma unroll
    for (int bb = 0; bb < BATCH; ++bb) {
        asm volatile(
            "st.global.v8.f32 [%0], {%1,%2,%3,%4,%5,%6,%7,%8};"
            :: "l"(dst),
               "f"(a.x), "f"(a.y), "f"(a.z), "f"(a.w),
               "f"(b.x), "f"(b.y), "f"(b.z), "f"(b.w)
            : "memory");
        dst += (size_t)E_PAIRS * 4;   // next batch image (floats)
    }
}

__global__ __launch_bounds__(THREADS)
void edge_onehot_v8_kernel(const float* __restrict__ adj, float* __restrict__ outf)
{
    const int bid = blockIdx.x;
    const int tid = threadIdx.x;

    // 128B-aligned per-CTA chunk, in v8 elements.
    const int units  = UNIT_LO + (bid < UREM ? 1 : 0);
    const int ustart = bid * UNIT_LO + (bid < UREM ? bid : UREM);
    const int cnt    = units * 4;           // 268 or 272 v8 elements
    const int qstart = ustart * 4;          // multiple of 4 -> 128B aligned

    // Slot 0: tid in [0, 256) — always < cnt (268/272).
    do_v8(adj, outf, qstart + tid);
    // Slot 1: [256, cnt) — 12 or 16 threads.
    const int idx = tid + THREADS;
    if (idx < cnt)
        do_v8(adj, outf, qstart + idx);
}

extern "C" void kernel_launch(void* const* d_in, const int* in_sizes, int n_in,
                              void* d_out, int out_size)
{
    // metadata order: inputs, weather, rel_rec, rel_send, adj_matrix
    const float* adj = (const float*)d_in[4];
    float* outf = (float*)d_out;

    edge_onehot_v8_kernel<<<GRID_X, THREADS>>>(adj, outf);
}